// round 11
// baseline (speedup 1.0000x reference)
#include <cuda_runtime.h>
#include <math_constants.h>

#define N 8192
#define D 512
#define BROWS 32      // rows per LSE block
#define WROWS 4       // rows per warp (serial)

// quantization: C stored as uint16, value = q / QSCALE, QSCALE = 1600 (max 40.96)
#define QSCALE    1600.0f
#define KC        28.85390081777927f          // 1/(eps*ln2)
#define QK        (KC / QSCALE)
#define EPSLN2    0.034657359027997264f       // eps*ln2
#define EPSLOGN   0.4505456673639644f         // eps*ln(8192)

// ---------------- device scratch (no allocations allowed) ----------------
__device__ __align__(256) unsigned short d_Cxy[67108864];   // 128MB each
__device__ __align__(256) unsigned short d_Cyx[67108864];
__device__ __align__(256) unsigned short d_Cxx[67108864];
__device__ __align__(256) unsigned short d_Cyy[67108864];
__device__ __align__(256) float d_sx[N];
__device__ __align__(256) float d_sy[N];
__device__ __align__(256) float d_vecs[2][4][N];   // ping-pong f,g,p,q
__device__ __align__(256) float d_evec[4][N];      // f_e, g_e, p_e, q_e

// ---------------- row squared-norms ----------------
__global__ void rownorm_kernel(const float* __restrict__ X, const float* __restrict__ PZ) {
    const float* src = (blockIdx.y == 0) ? PZ : X;    // y=0: xs=prior_z -> sx
    float* dst = (blockIdx.y == 0) ? d_sx : d_sy;
    int row = blockIdx.x * 8 + (threadIdx.x >> 5);
    int lane = threadIdx.x & 31;
    const float4* xr = (const float4*)(src + (size_t)row * D);
    float s = 0.f;
    #pragma unroll
    for (int t = lane; t < D / 4; t += 32) {
        float4 v = xr[t];
        s += v.x * v.x + v.y * v.y + v.z * v.z + v.w * v.w;
    }
    #pragma unroll
    for (int o = 16; o; o >>= 1) s += __shfl_down_sync(0xffffffffu, s, o);
    if (lane == 0) dst[row] = s;
}

__global__ void init_kernel() {
    int i = blockIdx.x * blockDim.x + threadIdx.x;
    if (i < 2 * 4 * N) ((float*)d_vecs)[i] = 0.f;
}

// ---------------- fused GEMM + distance + uint16 quantize ----------------
__global__ __launch_bounds__(256) void gemm_dist_kernel(
    const float* __restrict__ X, const float* __restrict__ PZ, int which)
{
    const float *A, *B, *sA, *sB;
    unsigned short *C, *Cm;
    bool sym;
    if (which == 0)      { A = PZ; B = X;  sA = d_sx; sB = d_sy; C = d_Cxy; Cm = d_Cyx; sym = false; }
    else if (which == 1) { A = PZ; B = PZ; sA = d_sx; sB = d_sx; C = d_Cxx; Cm = d_Cxx; sym = true;  }
    else                 { A = X;  B = X;  sA = d_sy; sB = d_sy; C = d_Cyy; Cm = d_Cyy; sym = true;  }

    int bx = blockIdx.x, by = blockIdx.y;
    if (sym && by > bx) return;   // triangular tiles only; mirror via transpose store

    __shared__ float As[16][132];
    __shared__ float Bs[16][132];
    __shared__ unsigned int ts[128][65];   // packed uint16 pairs, pad->conflict-free cols

    int tid = threadIdx.x;
    int ty = tid >> 4, tx = tid & 15;
    int trow = ty * 8, tcol = tx * 8;

    float acc[8][8];
    #pragma unroll
    for (int i = 0; i < 8; i++)
        #pragma unroll
        for (int j = 0; j < 8; j++) acc[i][j] = 0.f;

    const float* Ab = A + (size_t)by * 128 * D;
    const float* Bb = B + (size_t)bx * 128 * D;

    for (int k0 = 0; k0 < D; k0 += 16) {
        #pragma unroll
        for (int l = 0; l < 2; l++) {
            int idx = tid + l * 256;       // 0..511
            int r = idx >> 2;              // 0..127
            int c = (idx & 3) << 2;        // 0,4,8,12
            float4 av = *(const float4*)(Ab + (size_t)r * D + k0 + c);
            As[c + 0][r] = av.x; As[c + 1][r] = av.y; As[c + 2][r] = av.z; As[c + 3][r] = av.w;
            float4 bv = *(const float4*)(Bb + (size_t)r * D + k0 + c);
            Bs[c + 0][r] = bv.x; Bs[c + 1][r] = bv.y; Bs[c + 2][r] = bv.z; Bs[c + 3][r] = bv.w;
        }
        __syncthreads();
        #pragma unroll
        for (int kk = 0; kk < 16; kk++) {
            float ar[8], br[8];
            #pragma unroll
            for (int i = 0; i < 8; i++) ar[i] = As[kk][trow + i];
            #pragma unroll
            for (int j = 0; j < 8; j++) br[j] = Bs[kk][tcol + j];
            #pragma unroll
            for (int i = 0; i < 8; i++)
                #pragma unroll
                for (int j = 0; j < 8; j++)
                    acc[i][j] = fmaf(ar[i], br[j], acc[i][j]);
        }
        __syncthreads();
    }

    int gr0 = by * 128, gc0 = bx * 128;
    float sa[8], sb[8];
    #pragma unroll
    for (int i = 0; i < 8; i++) sa[i] = sA[gr0 + trow + i];
    #pragma unroll
    for (int j = 0; j < 8; j++) sb[j] = sB[gc0 + tcol + j];

    #pragma unroll
    for (int i = 0; i < 8; i++) {
        #pragma unroll
        for (int j = 0; j < 8; j += 2) {
            float sq0 = sa[i] + sb[j]     - 2.f * acc[i][j];
            float sq1 = sa[i] + sb[j + 1] - 2.f * acc[i][j + 1];
            float d0 = sqrtf(fmaxf(sq0, 1e-12f));
            float d1 = sqrtf(fmaxf(sq1, 1e-12f));
            unsigned int q0 = min(65535u, __float2uint_rn(d0 * QSCALE));
            unsigned int q1 = min(65535u, __float2uint_rn(d1 * QSCALE));
            ts[trow + i][(tcol + j) >> 1] = q0 | (q1 << 16);
        }
    }
    __syncthreads();

    for (int idx = tid; idx < 128 * 16; idx += 256) {
        int r = idx >> 4, seg = idx & 15;
        uint4 w;
        w.x = ts[r][seg * 4 + 0];
        w.y = ts[r][seg * 4 + 1];
        w.z = ts[r][seg * 4 + 2];
        w.w = ts[r][seg * 4 + 3];
        *(uint4*)&C[(size_t)(gr0 + r) * N + gc0 + seg * 8] = w;
    }
    for (int idx = tid; idx < 128 * 16; idx += 256) {
        int c = idx >> 4, seg = idx & 15;
        uint4 w;
        unsigned int sh = (c & 1) * 16;
        #pragma unroll
        for (int k = 0; k < 4; k++) {
            int r = seg * 8 + k * 2;
            unsigned int lo = (ts[r][c >> 1] >> sh) & 0xFFFFu;
            unsigned int hi = (ts[r + 1][c >> 1] >> sh) & 0xFFFFu;
            ((unsigned int*)&w)[k] = lo | (hi << 16);
        }
        *(uint4*)&Cm[(size_t)(gc0 + c) * N + gr0 + seg * 8] = w;
    }
}

// ---------------- warp-autonomous chunked LSE ----------------
// One warp per row (4 rows serially), no block barriers in the main loop.
// Row = 4 chunks of 8 uint4/lane; chunks double-buffered (prefetch chunk c+1
// or next row's chunk 0 before processing chunk c -> 128B/lane in flight).
// Chunk-level two-pass: pass1 decode -> group maxima; if chunk is within 25
// units of running max, rescale s once and re-decode surviving groups for exps.
// V pre-scaled (v*KC + BIG) once per block into smem vA/vB.
// mode=0: damped Sinkhorn update; mode=1: extrapolation
__global__ __launch_bounds__(256, 2) void lse_kernel(int parity, int mode) {
    int which = blockIdx.y;
    int tid = threadIdx.x;

    const float* base_r = &d_vecs[parity][0][0];
    float* base_w = &d_vecs[parity ^ 1][0][0];
    const unsigned short* Cq; const float* vin; const float* vold; float* vout;
    if (which == 0)      { Cq = d_Cxy; vin = base_r + N;     vold = base_r;         vout = base_w;         }
    else if (which == 1) { Cq = d_Cyx; vin = base_r;         vold = base_r + N;     vout = base_w + N;     }
    else if (which == 2) { Cq = d_Cxx; vin = base_r + 2 * N; vold = base_r + 2 * N; vout = base_w + 2 * N; }
    else                 { Cq = d_Cyy; vin = base_r + 3 * N; vold = base_r + 3 * N; vout = base_w + 3 * N; }
    if (mode) vout = &d_evec[which][0];

    const float nQK = -QK;
    const float BIG = QK * 8388608.0f;     // exact: QK * 2^23 (decode bias)

    // pre-scaled V in smem: vA[g] = cols 8g..8g+3, vB[g] = cols 8g+4..8g+7
    __shared__ float4 vA[N / 8];
    __shared__ float4 vB[N / 8];
    {
        const float4* V4 = (const float4*)vin;
        for (int g = tid; g < N / 8; g += 256) {
            float4 v0 = V4[2 * g], v1 = V4[2 * g + 1];
            vA[g] = make_float4(fmaf(v0.x, KC, BIG), fmaf(v0.y, KC, BIG),
                                fmaf(v0.z, KC, BIG), fmaf(v0.w, KC, BIG));
            vB[g] = make_float4(fmaf(v1.x, KC, BIG), fmaf(v1.y, KC, BIG),
                                fmaf(v1.z, KC, BIG), fmaf(v1.w, KC, BIG));
        }
    }
    __syncthreads();   // only block barrier in the kernel

    int wid = tid >> 5, lane = tid & 31;
    int row0 = blockIdx.x * BROWS + wid * WROWS;

    #define DEC2(uw, vka, vkb, a0, a1) \
        { float q0 = __uint_as_float(0x4B000000u | ((uw) & 0xFFFFu)); \
          float q1 = __uint_as_float(0x4B000000u | ((uw) >> 16)); \
          a0 = fmaf(q0, nQK, (vka)); \
          a1 = fmaf(q1, nQK, (vkb)); }

    float mx, s;

    auto prefetch = [&](uint4* b, int pr, int pc) {
        const uint4* P = (const uint4*)(Cq + (size_t)pr * N);
        #pragma unroll
        for (int k = 0; k < 8; k++) b[k] = P[pc * 256 + k * 32 + lane];
    };

    auto process = [&](const uint4* b, int c) {
        // pass 1: decode, per-group (8-elem) maxima
        float gm[8];
        float cm = -CUDART_INF_F;
        #pragma unroll
        for (int k = 0; k < 8; k++) {
            int g = c * 256 + k * 32 + lane;
            float4 va = vA[g], vb = vB[g];
            float a0, a1, a2, a3, a4, a5, a6, a7;
            DEC2(b[k].x, va.x, va.y, a0, a1);
            DEC2(b[k].y, va.z, va.w, a2, a3);
            DEC2(b[k].z, vb.x, vb.y, a4, a5);
            DEC2(b[k].w, vb.z, vb.w, a6, a7);
            float g8 = fmaxf(fmaxf(fmaxf(a0, a1), fmaxf(a2, a3)),
                             fmaxf(fmaxf(a4, a5), fmaxf(a6, a7)));
            gm[k] = g8;
            cm = fmaxf(cm, g8);
        }
        if (cm > mx - 25.f) {
            float M = fmaxf(mx, cm);
            float thr = M - 25.f;
            s *= exp2f(mx - M);          // rescale old sum (mx=-inf -> s stays 0)
            #pragma unroll
            for (int k = 0; k < 8; k++) {
                if (gm[k] > thr) {
                    int g = c * 256 + k * 32 + lane;
                    float4 va = vA[g], vb = vB[g];
                    float a0, a1, a2, a3, a4, a5, a6, a7;
                    DEC2(b[k].x, va.x, va.y, a0, a1);
                    DEC2(b[k].y, va.z, va.w, a2, a3);
                    DEC2(b[k].z, vb.x, vb.y, a4, a5);
                    DEC2(b[k].w, vb.z, vb.w, a6, a7);
                    if (a0 > thr) s += exp2f(a0 - M);
                    if (a1 > thr) s += exp2f(a1 - M);
                    if (a2 > thr) s += exp2f(a2 - M);
                    if (a3 > thr) s += exp2f(a3 - M);
                    if (a4 > thr) s += exp2f(a4 - M);
                    if (a5 > thr) s += exp2f(a5 - M);
                    if (a6 > thr) s += exp2f(a6 - M);
                    if (a7 > thr) s += exp2f(a7 - M);
                }
            }
            mx = M;
        }
    };

    uint4 bufA[8], bufB[8];
    prefetch(bufA, row0, 0);

    #pragma unroll 1
    for (int r = 0; r < WROWS; r++) {
        int row = row0 + r;
        int nrow = (row + 1 < N) ? row + 1 : row;   // clamped next-row prefetch
        mx = -CUDART_INF_F;
        s = 0.f;

        prefetch(bufB, row, 1);   process(bufA, 0);
        prefetch(bufA, row, 2);   process(bufB, 1);
        prefetch(bufB, row, 3);   process(bufA, 2);
        prefetch(bufA, nrow, 0);  process(bufB, 3);

        // lane merge of (mx, s)
        #pragma unroll
        for (int o = 16; o; o >>= 1) {
            float m2 = __shfl_xor_sync(0xffffffffu, mx, o);
            float s2 = __shfl_xor_sync(0xffffffffu, s, o);
            float M = fmaxf(mx, m2);
            s = s * exp2f(mx - M) + s2 * exp2f(m2 - M);
            mx = M;
        }

        if (lane == 0) {
            float lse2 = mx + log2f(s);
            float val;
            if (mode) val = EPSLOGN - EPSLN2 * lse2;
            else      val = 0.5f * (vold[row] + EPSLOGN - EPSLN2 * lse2);
            vout[row] = val;
        }
    }
    #undef DEC2
}

// ---------------- final scalar reduction ----------------
__global__ void final_kernel(float* out) {
    __shared__ double sh[32];
    double acc = 0.0;
    for (int i = threadIdx.x; i < N; i += 1024) {
        acc += (double)d_evec[0][i] - (double)d_evec[2][i]
             + (double)d_evec[1][i] - (double)d_evec[3][i];
    }
    #pragma unroll
    for (int o = 16; o; o >>= 1) acc += __shfl_down_sync(0xffffffffu, acc, o);
    int w = threadIdx.x >> 5, lane = threadIdx.x & 31;
    if (lane == 0) sh[w] = acc;
    __syncthreads();
    if (threadIdx.x < 32) {
        double a = sh[threadIdx.x];
        #pragma unroll
        for (int o = 16; o; o >>= 1) a += __shfl_down_sync(0xffffffffu, a, o);
        if (threadIdx.x == 0) out[0] = (float)(a / (double)N);
    }
}

// ---------------- launch ----------------
extern "C" void kernel_launch(void* const* d_in, const int* in_sizes, int n_in,
                              void* d_out, int out_size) {
    (void)in_sizes; (void)n_in; (void)out_size;
    const float* x  = (const float*)d_in[0];   // xt
    const float* pz = (const float*)d_in[1];   // xs

    rownorm_kernel<<<dim3(N / 8, 2), 256>>>(x, pz);
    init_kernel<<<(2 * 4 * N + 255) / 256, 256>>>();

    dim3 gg(64, 64);
    gemm_dist_kernel<<<gg, 256>>>(x, pz, 0);
    gemm_dist_kernel<<<gg, 256>>>(x, pz, 1);
    gemm_dist_kernel<<<gg, 256>>>(x, pz, 2);

    for (int it = 0; it < 50; ++it)
        lse_kernel<<<dim3(N / BROWS, 4), 256>>>(it & 1, 0);

    lse_kernel<<<dim3(N / BROWS, 4), 256>>>(0, 1);   // extrapolation (final vecs in slot 0)
    final_kernel<<<1, 1024>>>((float*)d_out);
}

// round 12
// speedup vs baseline: 1.5761x; 1.5761x over previous
#include <cuda_runtime.h>
#include <math_constants.h>

#define N 8192
#define D 512
#define ROWS 16      // rows per LSE block
#define BOOT 12      // bootstrap iterations using two-pass kernel

// quantization: C stored as uint16, value = q / QSCALE, QSCALE = 1600 (max 40.96)
#define QSCALE    1600.0f
#define KC        28.85390081777927f          // 1/(eps*ln2)
#define QK        (KC / QSCALE)
#define EPSLN2    0.034657359027997264f       // eps*ln2
#define EPSLOGN   0.4505456673639644f         // eps*ln(8192)

// ---------------- device scratch (no allocations allowed) ----------------
__device__ __align__(256) unsigned short d_Cxy[67108864];   // 128MB each
__device__ __align__(256) unsigned short d_Cyx[67108864];
__device__ __align__(256) unsigned short d_Cxx[67108864];
__device__ __align__(256) unsigned short d_Cyy[67108864];
__device__ __align__(256) float d_sx[N];
__device__ __align__(256) float d_sy[N];
__device__ __align__(256) float d_vecs[2][4][N];   // ping-pong f,g,p,q
__device__ __align__(256) float d_evec[4][N];      // f_e, g_e, p_e, q_e
__device__ __align__(256) float d_ref[4][N];       // last row-lse2 per matrix (base-2 units)

// ---------------- row squared-norms ----------------
__global__ void rownorm_kernel(const float* __restrict__ X, const float* __restrict__ PZ) {
    const float* src = (blockIdx.y == 0) ? PZ : X;    // y=0: xs=prior_z -> sx
    float* dst = (blockIdx.y == 0) ? d_sx : d_sy;
    int row = blockIdx.x * 8 + (threadIdx.x >> 5);
    int lane = threadIdx.x & 31;
    const float4* xr = (const float4*)(src + (size_t)row * D);
    float s = 0.f;
    #pragma unroll
    for (int t = lane; t < D / 4; t += 32) {
        float4 v = xr[t];
        s += v.x * v.x + v.y * v.y + v.z * v.z + v.w * v.w;
    }
    #pragma unroll
    for (int o = 16; o; o >>= 1) s += __shfl_down_sync(0xffffffffu, s, o);
    if (lane == 0) dst[row] = s;
}

__global__ void init_kernel() {
    int i = blockIdx.x * blockDim.x + threadIdx.x;
    if (i < 2 * 4 * N) ((float*)d_vecs)[i] = 0.f;
}

// ---------------- fused GEMM + distance + uint16 quantize ----------------
__global__ __launch_bounds__(256) void gemm_dist_kernel(
    const float* __restrict__ X, const float* __restrict__ PZ, int which)
{
    const float *A, *B, *sA, *sB;
    unsigned short *C, *Cm;
    bool sym;
    if (which == 0)      { A = PZ; B = X;  sA = d_sx; sB = d_sy; C = d_Cxy; Cm = d_Cyx; sym = false; }
    else if (which == 1) { A = PZ; B = PZ; sA = d_sx; sB = d_sx; C = d_Cxx; Cm = d_Cxx; sym = true;  }
    else                 { A = X;  B = X;  sA = d_sy; sB = d_sy; C = d_Cyy; Cm = d_Cyy; sym = true;  }

    int bx = blockIdx.x, by = blockIdx.y;
    if (sym && by > bx) return;   // triangular tiles only; mirror via transpose store

    __shared__ float As[16][132];
    __shared__ float Bs[16][132];
    __shared__ unsigned int ts[128][65];   // packed uint16 pairs, pad->conflict-free cols

    int tid = threadIdx.x;
    int ty = tid >> 4, tx = tid & 15;
    int trow = ty * 8, tcol = tx * 8;

    float acc[8][8];
    #pragma unroll
    for (int i = 0; i < 8; i++)
        #pragma unroll
        for (int j = 0; j < 8; j++) acc[i][j] = 0.f;

    const float* Ab = A + (size_t)by * 128 * D;
    const float* Bb = B + (size_t)bx * 128 * D;

    for (int k0 = 0; k0 < D; k0 += 16) {
        #pragma unroll
        for (int l = 0; l < 2; l++) {
            int idx = tid + l * 256;       // 0..511
            int r = idx >> 2;              // 0..127
            int c = (idx & 3) << 2;        // 0,4,8,12
            float4 av = *(const float4*)(Ab + (size_t)r * D + k0 + c);
            As[c + 0][r] = av.x; As[c + 1][r] = av.y; As[c + 2][r] = av.z; As[c + 3][r] = av.w;
            float4 bv = *(const float4*)(Bb + (size_t)r * D + k0 + c);
            Bs[c + 0][r] = bv.x; Bs[c + 1][r] = bv.y; Bs[c + 2][r] = bv.z; Bs[c + 3][r] = bv.w;
        }
        __syncthreads();
        #pragma unroll
        for (int kk = 0; kk < 16; kk++) {
            float ar[8], br[8];
            #pragma unroll
            for (int i = 0; i < 8; i++) ar[i] = As[kk][trow + i];
            #pragma unroll
            for (int j = 0; j < 8; j++) br[j] = Bs[kk][tcol + j];
            #pragma unroll
            for (int i = 0; i < 8; i++)
                #pragma unroll
                for (int j = 0; j < 8; j++)
                    acc[i][j] = fmaf(ar[i], br[j], acc[i][j]);
        }
        __syncthreads();
    }

    int gr0 = by * 128, gc0 = bx * 128;
    float sa[8], sb[8];
    #pragma unroll
    for (int i = 0; i < 8; i++) sa[i] = sA[gr0 + trow + i];
    #pragma unroll
    for (int j = 0; j < 8; j++) sb[j] = sB[gc0 + tcol + j];

    #pragma unroll
    for (int i = 0; i < 8; i++) {
        #pragma unroll
        for (int j = 0; j < 8; j += 2) {
            float sq0 = sa[i] + sb[j]     - 2.f * acc[i][j];
            float sq1 = sa[i] + sb[j + 1] - 2.f * acc[i][j + 1];
            float d0 = sqrtf(fmaxf(sq0, 1e-12f));
            float d1 = sqrtf(fmaxf(sq1, 1e-12f));
            unsigned int q0 = min(65535u, __float2uint_rn(d0 * QSCALE));
            unsigned int q1 = min(65535u, __float2uint_rn(d1 * QSCALE));
            ts[trow + i][(tcol + j) >> 1] = q0 | (q1 << 16);
        }
    }
    __syncthreads();

    for (int idx = tid; idx < 128 * 16; idx += 256) {
        int r = idx >> 4, seg = idx & 15;
        uint4 w;
        w.x = ts[r][seg * 4 + 0];
        w.y = ts[r][seg * 4 + 1];
        w.z = ts[r][seg * 4 + 2];
        w.w = ts[r][seg * 4 + 3];
        *(uint4*)&C[(size_t)(gr0 + r) * N + gc0 + seg * 8] = w;
    }
    for (int idx = tid; idx < 128 * 16; idx += 256) {
        int c = idx >> 4, seg = idx & 15;
        uint4 w;
        unsigned int sh = (c & 1) * 16;
        #pragma unroll
        for (int k = 0; k < 4; k++) {
            int r = seg * 8 + k * 2;
            unsigned int lo = (ts[r][c >> 1] >> sh) & 0xFFFFu;
            unsigned int hi = (ts[r + 1][c >> 1] >> sh) & 0xFFFFu;
            ((unsigned int*)&w)[k] = lo | (hi << 16);
        }
        *(uint4*)&Cm[(size_t)(gc0 + c) * N + gr0 + seg * 8] = w;
    }
}

// shared operand-selection helper for LSE kernels
#define LSE_SELECT() \
    const float* base_r = &d_vecs[parity][0][0]; \
    float* base_w = &d_vecs[parity ^ 1][0][0]; \
    const unsigned short* Cq; const float* vin; const float* vold; float* vout; \
    if (which == 0)      { Cq = d_Cxy; vin = base_r + N;     vold = base_r;         vout = base_w;         } \
    else if (which == 1) { Cq = d_Cyx; vin = base_r;         vold = base_r + N;     vout = base_w + N;     } \
    else if (which == 2) { Cq = d_Cxx; vin = base_r + 2 * N; vold = base_r + 2 * N; vout = base_w + 2 * N; } \
    else                 { Cq = d_Cyy; vin = base_r + 3 * N; vold = base_r + 3 * N; vout = base_w + 3 * N; }

#define DEC2(uw, vka, vkb, a0, a1) \
    { float q0 = __uint_as_float(0x4B000000u | ((uw) & 0xFFFFu)); \
      float q1 = __uint_as_float(0x4B000000u | ((uw) >> 16)); \
      a0 = fmaf(q0, nQK, (vka)); \
      a1 = fmaf(q1, nQK, (vkb)); }

// ---------------- two-pass LSE (bootstrap; also writes d_ref) ----------------
// Exact R9 structure: 16 rows/block, depth-2 prefetch, block max + thresholded sum.
__global__ __launch_bounds__(256, 2) void lse2_kernel(int parity) {
    int row0 = blockIdx.x * ROWS;
    int which = blockIdx.y;
    int tid = threadIdx.x;
    LSE_SELECT();
    float* refp = &d_ref[which][0];

    const float nQK = -QK;
    const float BIG = QK * 8388608.0f;   // exact: QK * 2^23 (decode bias)
    const float4* V4 = (const float4*)vin;

    float vrK[4][8];
    #pragma unroll
    for (int it = 0; it < 4; it++) {
        int base = it * 256 + tid;
        float4 v0 = V4[base * 2];
        float4 v1 = V4[base * 2 + 1];
        vrK[it][0] = fmaf(v0.x, KC, BIG); vrK[it][1] = fmaf(v0.y, KC, BIG);
        vrK[it][2] = fmaf(v0.z, KC, BIG); vrK[it][3] = fmaf(v0.w, KC, BIG);
        vrK[it][4] = fmaf(v1.x, KC, BIG); vrK[it][5] = fmaf(v1.y, KC, BIG);
        vrK[it][6] = fmaf(v1.z, KC, BIG); vrK[it][7] = fmaf(v1.w, KC, BIG);
    }

    const unsigned short* Cb = Cq + (size_t)row0 * N;
    uint4 cur[4], nxt[4], nxt2[4];
    #pragma unroll
    for (int it = 0; it < 4; it++)
        cur[it] = ((const uint4*)Cb)[it * 256 + tid];
    {
        const uint4* Cn = (const uint4*)(Cb + (size_t)N);
        #pragma unroll
        for (int it = 0; it < 4; it++)
            nxt[it] = Cn[it * 256 + tid];
    }

    __shared__ float sm[8];
    __shared__ float ssum[8];
    int w = tid >> 5, lane = tid & 31;

    #pragma unroll 4
    for (int r = 0; r < ROWS; r++) {
        if (r + 2 < ROWS) {
            const uint4* Cn = (const uint4*)(Cb + (size_t)(r + 2) * N);
            #pragma unroll
            for (int it = 0; it < 4; it++) nxt2[it] = Cn[it * 256 + tid];
        }

        float gm[4];
        float m = -CUDART_INF_F;
        #pragma unroll
        for (int it = 0; it < 4; it++) {
            float a0, a1, a2, a3, a4, a5, a6, a7;
            DEC2(cur[it].x, vrK[it][0], vrK[it][1], a0, a1);
            DEC2(cur[it].y, vrK[it][2], vrK[it][3], a2, a3);
            DEC2(cur[it].z, vrK[it][4], vrK[it][5], a4, a5);
            DEC2(cur[it].w, vrK[it][6], vrK[it][7], a6, a7);
            float g = fmaxf(fmaxf(fmaxf(a0, a1), fmaxf(a2, a3)),
                            fmaxf(fmaxf(a4, a5), fmaxf(a6, a7)));
            gm[it] = g;
            m = fmaxf(m, g);
        }
        #pragma unroll
        for (int o = 16; o; o >>= 1) m = fmaxf(m, __shfl_xor_sync(0xffffffffu, m, o));
        if (lane == 0) sm[w] = m;
        __syncthreads();
        float Mx = sm[0];
        #pragma unroll
        for (int i = 1; i < 8; i++) Mx = fmaxf(Mx, sm[i]);

        float thr = Mx - 25.f;
        float s = 0.f;
        #pragma unroll
        for (int it = 0; it < 4; it++) {
            if (__ballot_sync(0xffffffffu, gm[it] > thr)) {
                float a0, a1, a2, a3, a4, a5, a6, a7;
                DEC2(cur[it].x, vrK[it][0], vrK[it][1], a0, a1);
                DEC2(cur[it].y, vrK[it][2], vrK[it][3], a2, a3);
                DEC2(cur[it].z, vrK[it][4], vrK[it][5], a4, a5);
                DEC2(cur[it].w, vrK[it][6], vrK[it][7], a6, a7);
                if (a0 > thr) s += exp2f(a0 - Mx);
                if (a1 > thr) s += exp2f(a1 - Mx);
                if (a2 > thr) s += exp2f(a2 - Mx);
                if (a3 > thr) s += exp2f(a3 - Mx);
                if (a4 > thr) s += exp2f(a4 - Mx);
                if (a5 > thr) s += exp2f(a5 - Mx);
                if (a6 > thr) s += exp2f(a6 - Mx);
                if (a7 > thr) s += exp2f(a7 - Mx);
            }
        }
        #pragma unroll
        for (int o = 16; o; o >>= 1) s += __shfl_xor_sync(0xffffffffu, s, o);
        if (lane == 0) ssum[w] = s;
        __syncthreads();

        if (tid == 0) {
            float S = ssum[0];
            #pragma unroll
            for (int i = 1; i < 8; i++) S += ssum[i];
            float lse2 = Mx + log2f(S);
            vout[row0 + r] = 0.5f * (vold[row0 + r] + EPSLOGN - EPSLN2 * lse2);
            refp[row0 + r] = lse2;     // reference for the single-pass phase
        }

        #pragma unroll
        for (int it = 0; it < 4; it++) { cur[it] = nxt[it]; nxt[it] = nxt2[it]; }
    }
}

// ---------------- single-pass REF-based LSE ----------------
// Uses previous iteration's lse2 as exponent reference: no max reduction,
// one barrier per row (double-buffered partial sums), exp2 only for groups
// above R-30 (a's already decoded in registers).
// mode=0: damped update (writes vout + refreshes ref); mode=1: extrapolation.
__global__ __launch_bounds__(256, 2) void lse1_kernel(int parity, int mode) {
    int row0 = blockIdx.x * ROWS;
    int which = blockIdx.y;
    int tid = threadIdx.x;
    LSE_SELECT();
    if (mode) vout = &d_evec[which][0];
    float* refp = &d_ref[which][0];

    const float nQK = -QK;
    const float BIG = QK * 8388608.0f;
    const float4* V4 = (const float4*)vin;

    float vrK[4][8];
    #pragma unroll
    for (int it = 0; it < 4; it++) {
        int base = it * 256 + tid;
        float4 v0 = V4[base * 2];
        float4 v1 = V4[base * 2 + 1];
        vrK[it][0] = fmaf(v0.x, KC, BIG); vrK[it][1] = fmaf(v0.y, KC, BIG);
        vrK[it][2] = fmaf(v0.z, KC, BIG); vrK[it][3] = fmaf(v0.w, KC, BIG);
        vrK[it][4] = fmaf(v1.x, KC, BIG); vrK[it][5] = fmaf(v1.y, KC, BIG);
        vrK[it][6] = fmaf(v1.z, KC, BIG); vrK[it][7] = fmaf(v1.w, KC, BIG);
    }

    const unsigned short* Cb = Cq + (size_t)row0 * N;
    uint4 cur[4], nxt[4], nxt2[4];
    #pragma unroll
    for (int it = 0; it < 4; it++)
        cur[it] = ((const uint4*)Cb)[it * 256 + tid];
    {
        const uint4* Cn = (const uint4*)(Cb + (size_t)N);
        #pragma unroll
        for (int it = 0; it < 4; it++)
            nxt[it] = Cn[it * 256 + tid];
    }

    __shared__ float ssum[2][8];
    int w = tid >> 5, lane = tid & 31;

    #pragma unroll 4
    for (int r = 0; r < ROWS; r++) {
        if (r + 2 < ROWS) {
            const uint4* Cn = (const uint4*)(Cb + (size_t)(r + 2) * N);
            #pragma unroll
            for (int it = 0; it < 4; it++) nxt2[it] = Cn[it * 256 + tid];
        }

        float R = refp[row0 + r];          // uniform broadcast
        float thr = R - 30.f;
        float s = 0.f;
        #pragma unroll
        for (int it = 0; it < 4; it++) {
            float a0, a1, a2, a3, a4, a5, a6, a7;
            DEC2(cur[it].x, vrK[it][0], vrK[it][1], a0, a1);
            DEC2(cur[it].y, vrK[it][2], vrK[it][3], a2, a3);
            DEC2(cur[it].z, vrK[it][4], vrK[it][5], a4, a5);
            DEC2(cur[it].w, vrK[it][6], vrK[it][7], a6, a7);
            float g = fmaxf(fmaxf(fmaxf(a0, a1), fmaxf(a2, a3)),
                            fmaxf(fmaxf(a4, a5), fmaxf(a6, a7)));
            if (__ballot_sync(0xffffffffu, g > thr)) {
                if (a0 > thr) s += exp2f(a0 - R);
                if (a1 > thr) s += exp2f(a1 - R);
                if (a2 > thr) s += exp2f(a2 - R);
                if (a3 > thr) s += exp2f(a3 - R);
                if (a4 > thr) s += exp2f(a4 - R);
                if (a5 > thr) s += exp2f(a5 - R);
                if (a6 > thr) s += exp2f(a6 - R);
                if (a7 > thr) s += exp2f(a7 - R);
            }
        }
        #pragma unroll
        for (int o = 16; o; o >>= 1) s += __shfl_xor_sync(0xffffffffu, s, o);
        if (lane == 0) ssum[r & 1][w] = s;
        __syncthreads();

        if (tid == 0) {
            float S = ssum[r & 1][0];
            #pragma unroll
            for (int i = 1; i < 8; i++) S += ssum[r & 1][i];
            float lse2 = R + log2f(S);
            float val;
            if (mode) val = EPSLOGN - EPSLN2 * lse2;
            else      val = 0.5f * (vold[row0 + r] + EPSLOGN - EPSLN2 * lse2);
            vout[row0 + r] = val;
            if (!mode) refp[row0 + r] = lse2;   // self-correcting reference
        }

        #pragma unroll
        for (int it = 0; it < 4; it++) { cur[it] = nxt[it]; nxt[it] = nxt2[it]; }
    }
}

// ---------------- final scalar reduction ----------------
__global__ void final_kernel(float* out) {
    __shared__ double sh[32];
    double acc = 0.0;
    for (int i = threadIdx.x; i < N; i += 1024) {
        acc += (double)d_evec[0][i] - (double)d_evec[2][i]
             + (double)d_evec[1][i] - (double)d_evec[3][i];
    }
    #pragma unroll
    for (int o = 16; o; o >>= 1) acc += __shfl_down_sync(0xffffffffu, acc, o);
    int w = threadIdx.x >> 5, lane = threadIdx.x & 31;
    if (lane == 0) sh[w] = acc;
    __syncthreads();
    if (threadIdx.x < 32) {
        double a = sh[threadIdx.x];
        #pragma unroll
        for (int o = 16; o; o >>= 1) a += __shfl_down_sync(0xffffffffu, a, o);
        if (threadIdx.x == 0) out[0] = (float)(a / (double)N);
    }
}

// ---------------- launch ----------------
extern "C" void kernel_launch(void* const* d_in, const int* in_sizes, int n_in,
                              void* d_out, int out_size) {
    (void)in_sizes; (void)n_in; (void)out_size;
    const float* x  = (const float*)d_in[0];   // xt
    const float* pz = (const float*)d_in[1];   // xs

    rownorm_kernel<<<dim3(N / 8, 2), 256>>>(x, pz);
    init_kernel<<<(2 * 4 * N + 255) / 256, 256>>>();

    dim3 gg(64, 64);
    gemm_dist_kernel<<<gg, 256>>>(x, pz, 0);
    gemm_dist_kernel<<<gg, 256>>>(x, pz, 1);
    gemm_dist_kernel<<<gg, 256>>>(x, pz, 2);

    dim3 lg(N / ROWS, 4);
    for (int it = 0; it < BOOT; ++it)
        lse2_kernel<<<lg, 256>>>(it & 1);              // two-pass, writes refs
    for (int it = BOOT; it < 50; ++it)
        lse1_kernel<<<lg, 256>>>(it & 1, 0);           // single-pass w/ refs

    lse1_kernel<<<lg, 256>>>(0, 1);                    // extrapolation (final vecs in slot 0)
    final_kernel<<<1, 1024>>>((float*)d_out);
}